// round 1
// baseline (speedup 1.0000x reference)
#include <cuda_runtime.h>
#include <cstdint>

// ---------------- problem constants ----------------
#define Bsz 512
#define Wln 50
#define Tln 50
#define Hd  1024
#define Vb  1024
#define MVd 64
#define Ld  30
#define G4H 4096
#define SOS_INDEX 0
#define EOS_INDEX 1

// ---------------- scratch (device globals; no runtime alloc) ----------------
__device__ float d_r   [Bsz * Hd];            // attention-pooled set repr
__device__ float d_g   [Bsz * G4H];           // gate pre-activations
__device__ float d_h   [Bsz * Hd];            // recurrent h state (enc->gen, then menc)
__device__ float d_c   [Bsz * Hd];            // recurrent c state
__device__ float d_msg [Ld * Bsz * MVd];      // gen messages (probs)
__device__ float d_mm  [Ld * Bsz];            // msg_mask (mask BEFORE update)
__device__ float d_m   [Bsz];                 // running eos mask
__device__ float d_hall[Tln * Bsz * Hd];      // all dec hidden states

// ---------------- fp32 tiled GEMM: C[M,N] = A1@W1^T + A2@W2^T + b1 + b2 ----
// A row-major (M x K), W row-major (N x K)  (both K-contiguous -> "NT" GEMM)
// A1 supports gather (row m = A1 + gidx[m]*lda1) and broadcast (lda1 = 0).
__device__ __forceinline__ void gemm_part(
    float (&acc)[8][8], float (*As)[132], float (*Ws)[132],
    const float* arow, const float* wrow, int K,
    int lr, int lc, int tx, int ty)
{
    for (int k0 = 0; k0 < K; k0 += 8) {
        float4 av = *(const float4*)(arow + k0 + lc);
        float4 wv = *(const float4*)(wrow + k0 + lc);
        As[lc+0][lr]=av.x; As[lc+1][lr]=av.y; As[lc+2][lr]=av.z; As[lc+3][lr]=av.w;
        Ws[lc+0][lr]=wv.x; Ws[lc+1][lr]=wv.y; Ws[lc+2][lr]=wv.z; Ws[lc+3][lr]=wv.w;
        __syncthreads();
        #pragma unroll
        for (int k = 0; k < 8; k++) {
            const float4 a0 = *(const float4*)&As[k][ty*8];
            const float4 a1 = *(const float4*)&As[k][ty*8+4];
            const float4 w0 = *(const float4*)&Ws[k][tx*8];
            const float4 w1 = *(const float4*)&Ws[k][tx*8+4];
            float a[8] = {a0.x,a0.y,a0.z,a0.w,a1.x,a1.y,a1.z,a1.w};
            float w[8] = {w0.x,w0.y,w0.z,w0.w,w1.x,w1.y,w1.z,w1.w};
            #pragma unroll
            for (int i = 0; i < 8; i++)
                #pragma unroll
                for (int j = 0; j < 8; j++)
                    acc[i][j] = fmaf(a[i], w[j], acc[i][j]);
        }
        __syncthreads();
    }
}

__global__ void __launch_bounds__(256, 2)
gemm_dual(float* C, int N,
          const float* A1, int lda1, const int* __restrict__ gidx,
          const float* W1, int K1,
          const float* A2, const float* W2, int K2,
          const float* __restrict__ b1, const float* __restrict__ b2)
{
    __shared__ float As[8][132];
    __shared__ float Ws[8][132];
    const int bm = blockIdx.y * 128;
    const int bn = blockIdx.x * 128;
    const int tid = threadIdx.x;
    const int lr = tid >> 1;            // 0..127 (loader row within tile)
    const int lc = (tid & 1) << 2;      // 0 or 4 (loader col group)
    const int tx = tid & 15;            // compute col group
    const int ty = tid >> 4;            // compute row group

    float acc[8][8];
    #pragma unroll
    for (int i = 0; i < 8; i++)
        #pragma unroll
        for (int j = 0; j < 8; j++) acc[i][j] = 0.f;

    if (K1 > 0) {
        const float* arow = gidx ? (A1 + (size_t)gidx[bm + lr] * lda1)
                                 : (A1 + (size_t)(bm + lr) * lda1);
        const float* wrow = W1 + (size_t)(bn + lr) * K1;
        gemm_part(acc, As, Ws, arow, wrow, K1, lr, lc, tx, ty);
    }
    if (K2 > 0) {
        const float* arow = A2 + (size_t)(bm + lr) * K2;
        const float* wrow = W2 + (size_t)(bn + lr) * K2;
        gemm_part(acc, As, Ws, arow, wrow, K2, lr, lc, tx, ty);
    }

    #pragma unroll
    for (int i = 0; i < 8; i++) {
        const int m = bm + ty * 8 + i;
        float* crow = C + (size_t)m * N + bn + tx * 8;
        #pragma unroll
        for (int j = 0; j < 8; j++) {
            const int n = bn + tx * 8 + j;
            float v = acc[i][j];
            if (b1) v += b1[n];
            if (b2) v += b2[n];
            crow[j] = v;
        }
    }
}

// ---------------- LSTM elementwise update ----------------
// g layout: [b][4H] with i = [0,H), f = [H,2H), g = [2H,3H), o = [3H,4H)
__global__ void lstm_update(const float* __restrict__ g, const float* c_in,
                            float* h_out, float* c_out,
                            const float* __restrict__ mask, const float* h_old)
{
    int idx = blockIdx.x * blockDim.x + threadIdx.x;
    if (idx >= Bsz * Hd) return;
    int b  = idx >> 10;
    int hh = idx & 1023;
    const float* gb = g + ((size_t)b << 12);
    float gi = gb[hh], gf = gb[1024 + hh], gc = gb[2048 + hh], go = gb[3072 + hh];
    float cold = c_in ? c_in[idx] : 0.f;
    float si = 1.f / (1.f + expf(-gi));
    float sf = 1.f / (1.f + expf(-gf));
    float so = 1.f / (1.f + expf(-go));
    float cn = sf * cold + si * tanhf(gc);
    float hn = so * tanhf(cn);
    if (mask) {
        float mt = mask[b];
        hn = mt * hn + (1.f - mt) * h_old[idx];
        cn = mt * cn + (1.f - mt) * cold;
    }
    h_out[idx] = hn;
    c_out[idx] = cn;
}

// ---------------- attention + pooled representation ----------------
__global__ void attn_r(const int* __restrict__ inp, const float* __restrict__ mask,
                       const float* __restrict__ emb, const float* __restrict__ attn_w,
                       const float* __restrict__ attn_b, float* __restrict__ r)
{
    const int b = blockIdx.x;
    const int tid = threadIdx.x;
    const int lane = tid & 31, wrp = tid >> 5;       // 8 warps
    __shared__ float aw[Wln];
    __shared__ int   idxs[Wln];
    if (tid < Wln) idxs[tid] = inp[b * Wln + tid];
    __syncthreads();
    const float* w2 = attn_w + Hd;                   // h0 part is zero
    for (int wi = wrp; wi < Wln; wi += 8) {
        const float* e = emb + (size_t)idxs[wi] * Hd;
        float acc = 0.f;
        for (int k = lane; k < Hd; k += 32) acc += e[k] * w2[k];
        #pragma unroll
        for (int o = 16; o; o >>= 1) acc += __shfl_xor_sync(0xffffffffu, acc, o);
        if (lane == 0) {
            float a = 1.f / (1.f + expf(-(acc + attn_b[0])));
            aw[wi] = a * mask[wi * Bsz + b];
        }
    }
    __syncthreads();
    for (int hh = tid; hh < Hd; hh += 256) {
        float acc = 0.f;
        #pragma unroll 5
        for (int wi = 0; wi < Wln; wi++)
            acc += aw[wi] * emb[(size_t)idxs[wi] * Hd + hh];
        r[b * Hd + hh] = acc;
    }
}

// ---------------- gen output head: GEMV + softmax + eos mask ----------------
__global__ void gen_out(const float* __restrict__ h, const float* __restrict__ outW,
                        const float* __restrict__ outb,
                        float* __restrict__ msg, float* __restrict__ msgmask,
                        float* __restrict__ m_state, int l)
{
    const int b = blockIdx.x;
    const int j = threadIdx.x;                       // 64 threads, 2 warps
    __shared__ float4 hs4[Hd / 4];
    __shared__ float  red[2];
    const float4* hrow = (const float4*)(h + (size_t)b * Hd);
    for (int k = j; k < Hd / 4; k += 64) hs4[k] = hrow[k];
    __syncthreads();

    float acc = outb[j];
    const float4* w4 = (const float4*)(outW + (size_t)j * Hd);
    #pragma unroll 4
    for (int k = 0; k < Hd / 4; k++) {
        float4 wv = w4[k];
        float4 hv = hs4[k];
        acc += wv.x * hv.x + wv.y * hv.y + wv.z * hv.z + wv.w * hv.w;
    }

    float vmax = acc;
    #pragma unroll
    for (int o = 16; o; o >>= 1) vmax = fmaxf(vmax, __shfl_xor_sync(0xffffffffu, vmax, o));
    if ((j & 31) == 0) red[j >> 5] = vmax;
    __syncthreads();
    vmax = fmaxf(red[0], red[1]);
    float e = expf(acc - vmax);
    float s = e;
    #pragma unroll
    for (int o = 16; o; o >>= 1) s += __shfl_xor_sync(0xffffffffu, s, o);
    __syncthreads();
    if ((j & 31) == 0) red[j >> 5] = s;
    __syncthreads();
    s = red[0] + red[1];
    float p = e / s;
    msg[(size_t)l * Bsz * MVd + b * MVd + j] = p;
    if (j == EOS_INDEX) {
        float mo = m_state[b];
        msgmask[l * Bsz + b] = mo;                   // mask BEFORE update
        m_state[b] = mo * (1.f - p);
    }
}

__global__ void fill_val(float* p, float v, int n)
{
    int i = blockIdx.x * blockDim.x + threadIdx.x;
    if (i < n) p[i] = v;
}

// ---------------- host orchestration ----------------
extern "C" void kernel_launch(void* const* d_in, const int* in_sizes, int n_in,
                              void* d_out, int out_size)
{
    // target_max_len is a python scalar; detect whether it appears as a size-1 input
    const int s = (in_sizes[3] == 1) ? 1 : 0;

    const int*   input_var  = (const int*)  d_in[0];
    const float* input_mask = (const float*)d_in[1];
    const int*   target_var = (const int*)  d_in[2];
    const float* embedding  = (const float*)d_in[3 + s];
    const float* attn_w     = (const float*)d_in[4 + s];
    const float* attn_b     = (const float*)d_in[5 + s];
    const float* set_Wih    = (const float*)d_in[6 + s];
    const float* set_bih    = (const float*)d_in[8 + s];
    const float* set_bhh    = (const float*)d_in[9 + s];
    // 10+s set_h0 (zeros), 11+s set_c0 (zeros), 12+s gen_x0 (zeros), 13+s gen_Wih (x==0)
    const float* gen_Whh    = (const float*)d_in[14 + s];
    const float* gen_bih    = (const float*)d_in[15 + s];
    const float* gen_bhh    = (const float*)d_in[16 + s];
    const float* gen_outW   = (const float*)d_in[17 + s];
    const float* gen_outb   = (const float*)d_in[18 + s];
    const float* menc_Wih   = (const float*)d_in[19 + s];
    const float* menc_Whh   = (const float*)d_in[20 + s];
    const float* menc_bih   = (const float*)d_in[21 + s];
    const float* menc_bhh   = (const float*)d_in[22 + s];
    // 23+s menc_h0 (zeros), 24+s menc_c0 (zeros)
    const float* dec_Wih    = (const float*)d_in[25 + s];
    const float* dec_Whh    = (const float*)d_in[26 + s];
    const float* dec_bih    = (const float*)d_in[27 + s];
    const float* dec_bhh    = (const float*)d_in[28 + s];
    const float* dec_outW   = (const float*)d_in[29 + s];
    const float* dec_outb   = (const float*)d_in[30 + s];
    float* out = (float*)d_out;

    float *r, *g, *h, *c, *msg, *mm, *m, *hall;
    cudaGetSymbolAddress((void**)&r,    d_r);
    cudaGetSymbolAddress((void**)&g,    d_g);
    cudaGetSymbolAddress((void**)&h,    d_h);
    cudaGetSymbolAddress((void**)&c,    d_c);
    cudaGetSymbolAddress((void**)&msg,  d_msg);
    cudaGetSymbolAddress((void**)&mm,   d_mm);
    cudaGetSymbolAddress((void**)&m,    d_m);
    cudaGetSymbolAddress((void**)&hall, d_hall);

    const dim3 gemm_grid(G4H / 128, Bsz / 128);      // (32, 4)
    const int  cell_blocks = (Bsz * Hd) / 256;       // 2048

    // 1) attention + pooled r
    attn_r<<<Bsz, 256>>>(input_var, input_mask, embedding, attn_w, attn_b, r);

    // 2) set encoder cell (h0 = c0 = 0 -> no Whh term, c_in = 0)
    gemm_dual<<<gemm_grid, 256>>>(g, G4H, r, Hd, nullptr, set_Wih, Hd,
                                  nullptr, nullptr, 0, set_bih, set_bhh);
    lstm_update<<<cell_blocks, 256>>>(g, nullptr, h, c, nullptr, nullptr);

    // 3) gen loop (x == 0 -> only h@Whh + biases)
    fill_val<<<2, 256>>>(m, 1.f, Bsz);
    for (int l = 0; l < Ld; l++) {
        gemm_dual<<<gemm_grid, 256>>>(g, G4H, nullptr, 0, nullptr, nullptr, 0,
                                      h, gen_Whh, Hd, gen_bih, gen_bhh);
        lstm_update<<<cell_blocks, 256>>>(g, c, h, c, nullptr, nullptr);
        gen_out<<<Bsz, 64>>>(h, gen_outW, gen_outb, msg, mm, m, l);
    }

    // 4) message encoder loop (h0 = c0 = 0)
    fill_val<<<cell_blocks, 256>>>(h, 0.f, Bsz * Hd);
    fill_val<<<cell_blocks, 256>>>(c, 0.f, Bsz * Hd);
    for (int l = 0; l < Ld; l++) {
        gemm_dual<<<gemm_grid, 256>>>(g, G4H,
                                      msg + (size_t)l * Bsz * MVd, MVd, nullptr, menc_Wih, MVd,
                                      h, menc_Whh, Hd, menc_bih, menc_bhh);
        lstm_update<<<cell_blocks, 256>>>(g, c, h, c, mm + l * Bsz, h);
    }

    // 5) decoder loop: fused [x;h] GEMM with embedding gather; h states -> hall
    for (int t = 0; t < Tln; t++) {
        const float* A1   = embedding + (size_t)SOS_INDEX * Hd;
        int          lda1 = (t == 0) ? 0 : Hd;
        const int*   gi   = (t == 0) ? nullptr : (target_var + (size_t)(t - 1) * Bsz);
        const float* hprev = (t == 0) ? h : (hall + (size_t)(t - 1) * Bsz * Hd);
        gemm_dual<<<gemm_grid, 256>>>(g, G4H, A1, lda1, gi, dec_Wih, Hd,
                                      hprev, dec_Whh, Hd, dec_bih, dec_bhh);
        lstm_update<<<cell_blocks, 256>>>(g, c, hall + (size_t)t * Bsz * Hd, c,
                                          nullptr, nullptr);
    }

    // 6) batched logits: (T*B, H) @ (V, H)^T + b -> d_out (T, B, V)
    gemm_dual<<<dim3(Vb / 128, (Tln * Bsz) / 128), 256>>>(
        out, Vb, hall, Hd, nullptr, dec_outW, Hd,
        nullptr, nullptr, 0, dec_outb, nullptr);
}

// round 2
// speedup vs baseline: 2.2486x; 2.2486x over previous
#include <cuda_runtime.h>
#include <cuda_bf16.h>
#include <cstdint>

// ---------------- problem constants ----------------
#define Bsz 512
#define Wln 50
#define Tln 50
#define Hd  1024
#define Vb  1024
#define MVd 64
#define Ld  30
#define G4H 4096
#define SOS_INDEX 0
#define EOS_INDEX 1

#define SM_STRIDE 24   // b16 elements per smem row (48 bytes) -> conflict-free frags

// ---------------- scratch (device globals; no runtime alloc) ----------------
__device__ float d_r   [Bsz * Hd];
__device__ float d_g   [Bsz * G4H];
__device__ float d_h   [Bsz * Hd];
__device__ float d_c   [Bsz * Hd];
__device__ float d_msg [Ld * Bsz * MVd];
__device__ float d_mm  [Ld * Bsz];
__device__ float d_m   [Bsz];
__device__ float d_hall[Tln * Bsz * Hd];

// ---------------- helpers ----------------
__device__ __forceinline__ void mma16816(float* c, const uint32_t* a, const uint32_t* b)
{
    asm volatile(
        "mma.sync.aligned.m16n8k16.row.col.f32.bf16.bf16.f32 "
        "{%0,%1,%2,%3}, {%4,%5,%6,%7}, {%8,%9}, {%0,%1,%2,%3};\n"
        : "+f"(c[0]), "+f"(c[1]), "+f"(c[2]), "+f"(c[3])
        : "r"(a[0]), "r"(a[1]), "r"(a[2]), "r"(a[3]), "r"(b[0]), "r"(b[1]));
}

// convert 8 fp32 -> 8 (hi,lo) bf16 pairs, store packed 2-at-a-time
__device__ __forceinline__ void conv8(const float4 v0, const float4 v1,
                                      unsigned short* hi, unsigned short* lo)
{
    float f[8] = {v0.x, v0.y, v0.z, v0.w, v1.x, v1.y, v1.z, v1.w};
    #pragma unroll
    for (int i = 0; i < 8; i += 2) {
        float x0 = f[i], x1 = f[i + 1];
        __nv_bfloat162 h2 = __floats2bfloat162_rn(x0, x1);
        float h0 = __bfloat162float(h2.x), h1 = __bfloat162float(h2.y);
        __nv_bfloat162 l2 = __floats2bfloat162_rn(x0 - h0, x1 - h1);
        *(uint32_t*)(hi + i) = *(const uint32_t*)&h2;
        *(uint32_t*)(lo + i) = *(const uint32_t*)&l2;
    }
}

// ---------------- bf16x3 tensor-core GEMM ----------------
// C[M,N] = A1@W1^T + A2@W2^T + b1 + b2 ; A row-major (M,K), W row-major (N,K).
// A1 supports gather (gidx) and broadcast (lda1 = 0). K1,K2 multiples of 16.
__global__ void __launch_bounds__(256, 1)
gemm_dual(float* C, int N,
          const float* A1, int lda1, const int* __restrict__ gidx,
          const float* W1, int K1,
          const float* A2, const float* W2, int K2,
          const float* __restrict__ b1, const float* __restrict__ b2)
{
    __shared__ unsigned short As[2][2][128][SM_STRIDE];   // [stage][hi/lo][row][k]
    __shared__ unsigned short Bs[2][2][128][SM_STRIDE];

    const int bm = blockIdx.y * 128;
    const int bn = blockIdx.x * 128;
    const int tid = threadIdx.x;
    const int wid = tid >> 5, lane = tid & 31;
    const int r = lane >> 2, q = lane & 3;
    const int wm = (wid >> 2) * 64;        // 2 warp rows
    const int wn = (wid & 3) * 32;         // 4 warp cols

    // loader mapping: 2 threads per row, each covers 8 consecutive k (2 float4)
    const int lrow = tid >> 1;
    const int lk   = (tid & 1) * 8;

    const float* arow1 = nullptr;
    const float* wrow1 = nullptr;
    const float* arow2 = nullptr;
    const float* wrow2 = nullptr;
    if (K1 > 0) {
        const int m = bm + lrow;
        arow1 = gidx ? (A1 + (size_t)gidx[m] * lda1)
                     : (A1 + (size_t)m * lda1);
        wrow1 = W1 + (size_t)(bn + lrow) * K1;
    }
    if (K2 > 0) {
        arow2 = A2 + (size_t)(bm + lrow) * K2;
        wrow2 = W2 + (size_t)(bn + lrow) * K2;
    }

    const int ns = ((K1 + K2) >> 4);

    float acc[4][4][4];
    #pragma unroll
    for (int mt = 0; mt < 4; mt++)
        #pragma unroll
        for (int nt = 0; nt < 4; nt++)
            #pragma unroll
            for (int i = 0; i < 4; i++) acc[mt][nt][i] = 0.f;

    float4 pa0, pa1, pw0, pw1;
    // prefetch step 0
    {
        const int k = 0;
        const float* ap = (k < K1) ? (arow1 + k) : (arow2 + (k - K1));
        const float* wp = (k < K1) ? (wrow1 + k) : (wrow2 + (k - K1));
        pa0 = *(const float4*)(ap + lk);
        pa1 = *(const float4*)(ap + lk + 4);
        pw0 = *(const float4*)(wp + lk);
        pw1 = *(const float4*)(wp + lk + 4);
    }
    // store stage 0
    conv8(pa0, pa1, &As[0][0][lrow][lk], &As[0][1][lrow][lk]);
    conv8(pw0, pw1, &Bs[0][0][lrow][lk], &Bs[0][1][lrow][lk]);

    int cur = 0;
    for (int s = 0; s < ns; s++) {
        __syncthreads();
        const bool more = (s + 1 < ns);
        if (more) {
            const int k = (s + 1) << 4;
            const float* ap = (k < K1) ? (arow1 + k) : (arow2 + (k - K1));
            const float* wp = (k < K1) ? (wrow1 + k) : (wrow2 + (k - K1));
            pa0 = *(const float4*)(ap + lk);
            pa1 = *(const float4*)(ap + lk + 4);
            pw0 = *(const float4*)(wp + lk);
            pw1 = *(const float4*)(wp + lk + 4);
        }

        // ---- load fragments from smem ----
        uint32_t ah[4][4], al[4][4], bh[4][2], bl[4][2];
        #pragma unroll
        for (int mt = 0; mt < 4; mt++) {
            const unsigned short* ph = &As[cur][0][wm + mt * 16 + r][0];
            const unsigned short* pl = &As[cur][1][wm + mt * 16 + r][0];
            ah[mt][0] = *(const uint32_t*)(ph + 2 * q);
            ah[mt][1] = *(const uint32_t*)(ph + 8 * SM_STRIDE + 2 * q);
            ah[mt][2] = *(const uint32_t*)(ph + 2 * q + 8);
            ah[mt][3] = *(const uint32_t*)(ph + 8 * SM_STRIDE + 2 * q + 8);
            al[mt][0] = *(const uint32_t*)(pl + 2 * q);
            al[mt][1] = *(const uint32_t*)(pl + 8 * SM_STRIDE + 2 * q);
            al[mt][2] = *(const uint32_t*)(pl + 2 * q + 8);
            al[mt][3] = *(const uint32_t*)(pl + 8 * SM_STRIDE + 2 * q + 8);
        }
        #pragma unroll
        for (int nt = 0; nt < 4; nt++) {
            const unsigned short* ph = &Bs[cur][0][wn + nt * 8 + r][0];
            const unsigned short* pl = &Bs[cur][1][wn + nt * 8 + r][0];
            bh[nt][0] = *(const uint32_t*)(ph + 2 * q);
            bh[nt][1] = *(const uint32_t*)(ph + 2 * q + 8);
            bl[nt][0] = *(const uint32_t*)(pl + 2 * q);
            bl[nt][1] = *(const uint32_t*)(pl + 2 * q + 8);
        }

        // ---- 3-product bf16x3 MMA ----
        #pragma unroll
        for (int mt = 0; mt < 4; mt++)
            #pragma unroll
            for (int nt = 0; nt < 4; nt++) {
                mma16816(acc[mt][nt], ah[mt], bh[nt]);
                mma16816(acc[mt][nt], ah[mt], bl[nt]);
                mma16816(acc[mt][nt], al[mt], bh[nt]);
            }

        if (more) {
            const int nxt = cur ^ 1;
            conv8(pa0, pa1, &As[nxt][0][lrow][lk], &As[nxt][1][lrow][lk]);
            conv8(pw0, pw1, &Bs[nxt][0][lrow][lk], &Bs[nxt][1][lrow][lk]);
        }
        cur ^= 1;
    }

    // ---- epilogue with biases ----
    #pragma unroll
    for (int nt = 0; nt < 4; nt++) {
        const int n0 = bn + wn + nt * 8 + 2 * q;
        float bias0 = 0.f, bias1 = 0.f;
        if (b1) { bias0 += b1[n0]; bias1 += b1[n0 + 1]; }
        if (b2) { bias0 += b2[n0]; bias1 += b2[n0 + 1]; }
        #pragma unroll
        for (int mt = 0; mt < 4; mt++) {
            const int m0 = bm + wm + mt * 16 + r;
            float2 v0 = make_float2(acc[mt][nt][0] + bias0, acc[mt][nt][1] + bias1);
            float2 v1 = make_float2(acc[mt][nt][2] + bias0, acc[mt][nt][3] + bias1);
            *(float2*)&C[(size_t)m0 * N + n0] = v0;
            *(float2*)&C[(size_t)(m0 + 8) * N + n0] = v1;
        }
    }
}

// ---------------- LSTM elementwise update ----------------
__global__ void lstm_update(const float* __restrict__ g, const float* c_in,
                            float* h_out, float* c_out,
                            const float* __restrict__ mask, const float* h_old)
{
    int idx = blockIdx.x * blockDim.x + threadIdx.x;
    if (idx >= Bsz * Hd) return;
    int b  = idx >> 10;
    int hh = idx & 1023;
    const float* gb = g + ((size_t)b << 12);
    float gi = gb[hh], gf = gb[1024 + hh], gc = gb[2048 + hh], go = gb[3072 + hh];
    float cold = c_in ? c_in[idx] : 0.f;
    float si = 1.f / (1.f + expf(-gi));
    float sf = 1.f / (1.f + expf(-gf));
    float so = 1.f / (1.f + expf(-go));
    float cn = sf * cold + si * tanhf(gc);
    float hn = so * tanhf(cn);
    if (mask) {
        float mt = mask[b];
        hn = mt * hn + (1.f - mt) * h_old[idx];
        cn = mt * cn + (1.f - mt) * cold;
    }
    h_out[idx] = hn;
    c_out[idx] = cn;
}

// ---------------- attention + pooled representation ----------------
__global__ void attn_r(const int* __restrict__ inp, const float* __restrict__ mask,
                       const float* __restrict__ emb, const float* __restrict__ attn_w,
                       const float* __restrict__ attn_b, float* __restrict__ r)
{
    const int b = blockIdx.x;
    const int tid = threadIdx.x;
    const int lane = tid & 31, wrp = tid >> 5;
    __shared__ float aw[Wln];
    __shared__ int   idxs[Wln];
    if (tid < Wln) idxs[tid] = inp[b * Wln + tid];
    __syncthreads();
    const float* w2 = attn_w + Hd;
    for (int wi = wrp; wi < Wln; wi += 8) {
        const float* e = emb + (size_t)idxs[wi] * Hd;
        float acc = 0.f;
        for (int k = lane; k < Hd; k += 32) acc += e[k] * w2[k];
        #pragma unroll
        for (int o = 16; o; o >>= 1) acc += __shfl_xor_sync(0xffffffffu, acc, o);
        if (lane == 0) {
            float a = 1.f / (1.f + expf(-(acc + attn_b[0])));
            aw[wi] = a * mask[wi * Bsz + b];
        }
    }
    __syncthreads();
    for (int hh = tid; hh < Hd; hh += 256) {
        float acc = 0.f;
        #pragma unroll 5
        for (int wi = 0; wi < Wln; wi++)
            acc += aw[wi] * emb[(size_t)idxs[wi] * Hd + hh];
        r[b * Hd + hh] = acc;
    }
}

// ---------------- gen output head: GEMV + softmax + eos mask ----------------
__global__ void gen_out(const float* __restrict__ h, const float* __restrict__ outW,
                        const float* __restrict__ outb,
                        float* __restrict__ msg, float* __restrict__ msgmask,
                        float* __restrict__ m_state, int l)
{
    const int b = blockIdx.x;
    const int j = threadIdx.x;
    __shared__ float4 hs4[Hd / 4];
    __shared__ float  red[2];
    const float4* hrow = (const float4*)(h + (size_t)b * Hd);
    for (int k = j; k < Hd / 4; k += 64) hs4[k] = hrow[k];
    __syncthreads();

    float acc = outb[j];
    const float4* w4 = (const float4*)(outW + (size_t)j * Hd);
    #pragma unroll 4
    for (int k = 0; k < Hd / 4; k++) {
        float4 wv = w4[k];
        float4 hv = hs4[k];
        acc += wv.x * hv.x + wv.y * hv.y + wv.z * hv.z + wv.w * hv.w;
    }

    float vmax = acc;
    #pragma unroll
    for (int o = 16; o; o >>= 1) vmax = fmaxf(vmax, __shfl_xor_sync(0xffffffffu, vmax, o));
    if ((j & 31) == 0) red[j >> 5] = vmax;
    __syncthreads();
    vmax = fmaxf(red[0], red[1]);
    float e = expf(acc - vmax);
    float s = e;
    #pragma unroll
    for (int o = 16; o; o >>= 1) s += __shfl_xor_sync(0xffffffffu, s, o);
    __syncthreads();
    if ((j & 31) == 0) red[j >> 5] = s;
    __syncthreads();
    s = red[0] + red[1];
    float p = e / s;
    msg[(size_t)l * Bsz * MVd + b * MVd + j] = p;
    if (j == EOS_INDEX) {
        float mo = m_state[b];
        msgmask[l * Bsz + b] = mo;
        m_state[b] = mo * (1.f - p);
    }
}

__global__ void fill_val(float* p, float v, int n)
{
    int i = blockIdx.x * blockDim.x + threadIdx.x;
    if (i < n) p[i] = v;
}

// ---------------- host orchestration ----------------
extern "C" void kernel_launch(void* const* d_in, const int* in_sizes, int n_in,
                              void* d_out, int out_size)
{
    const int s = (in_sizes[3] == 1) ? 1 : 0;

    const int*   input_var  = (const int*)  d_in[0];
    const float* input_mask = (const float*)d_in[1];
    const int*   target_var = (const int*)  d_in[2];
    const float* embedding  = (const float*)d_in[3 + s];
    const float* attn_w     = (const float*)d_in[4 + s];
    const float* attn_b     = (const float*)d_in[5 + s];
    const float* set_Wih    = (const float*)d_in[6 + s];
    const float* set_bih    = (const float*)d_in[8 + s];
    const float* set_bhh    = (const float*)d_in[9 + s];
    const float* gen_Whh    = (const float*)d_in[14 + s];
    const float* gen_bih    = (const float*)d_in[15 + s];
    const float* gen_bhh    = (const float*)d_in[16 + s];
    const float* gen_outW   = (const float*)d_in[17 + s];
    const float* gen_outb   = (const float*)d_in[18 + s];
    const float* menc_Wih   = (const float*)d_in[19 + s];
    const float* menc_Whh   = (const float*)d_in[20 + s];
    const float* menc_bih   = (const float*)d_in[21 + s];
    const float* menc_bhh   = (const float*)d_in[22 + s];
    const float* dec_Wih    = (const float*)d_in[25 + s];
    const float* dec_Whh    = (const float*)d_in[26 + s];
    const float* dec_bih    = (const float*)d_in[27 + s];
    const float* dec_bhh    = (const float*)d_in[28 + s];
    const float* dec_outW   = (const float*)d_in[29 + s];
    const float* dec_outb   = (const float*)d_in[30 + s];
    float* out = (float*)d_out;

    float *r, *g, *h, *c, *msg, *mm, *m, *hall;
    cudaGetSymbolAddress((void**)&r,    d_r);
    cudaGetSymbolAddress((void**)&g,    d_g);
    cudaGetSymbolAddress((void**)&h,    d_h);
    cudaGetSymbolAddress((void**)&c,    d_c);
    cudaGetSymbolAddress((void**)&msg,  d_msg);
    cudaGetSymbolAddress((void**)&mm,   d_mm);
    cudaGetSymbolAddress((void**)&m,    d_m);
    cudaGetSymbolAddress((void**)&hall, d_hall);

    const dim3 gemm_grid(G4H / 128, Bsz / 128);      // (32, 4)
    const int  cell_blocks = (Bsz * Hd) / 256;

    // 1) attention + pooled r
    attn_r<<<Bsz, 256>>>(input_var, input_mask, embedding, attn_w, attn_b, r);

    // 2) set encoder cell (h0 = c0 = 0)
    gemm_dual<<<gemm_grid, 256>>>(g, G4H, r, Hd, nullptr, set_Wih, Hd,
                                  nullptr, nullptr, 0, set_bih, set_bhh);
    lstm_update<<<cell_blocks, 256>>>(g, nullptr, h, c, nullptr, nullptr);

    // 3) gen loop (x == 0 -> only h@Whh + biases)
    fill_val<<<2, 256>>>(m, 1.f, Bsz);
    for (int l = 0; l < Ld; l++) {
        gemm_dual<<<gemm_grid, 256>>>(g, G4H, nullptr, 0, nullptr, nullptr, 0,
                                      h, gen_Whh, Hd, gen_bih, gen_bhh);
        lstm_update<<<cell_blocks, 256>>>(g, c, h, c, nullptr, nullptr);
        gen_out<<<Bsz, 64>>>(h, gen_outW, gen_outb, msg, mm, m, l);
    }

    // 4) message encoder loop (h0 = c0 = 0)
    fill_val<<<cell_blocks, 256>>>(h, 0.f, Bsz * Hd);
    fill_val<<<cell_blocks, 256>>>(c, 0.f, Bsz * Hd);
    for (int l = 0; l < Ld; l++) {
        gemm_dual<<<gemm_grid, 256>>>(g, G4H,
                                      msg + (size_t)l * Bsz * MVd, MVd, nullptr, menc_Wih, MVd,
                                      h, menc_Whh, Hd, menc_bih, menc_bhh);
        lstm_update<<<cell_blocks, 256>>>(g, c, h, c, mm + l * Bsz, h);
    }

    // 5) decoder loop: fused [x;h] GEMM with embedding gather
    for (int t = 0; t < Tln; t++) {
        const float* A1   = embedding + (size_t)SOS_INDEX * Hd;
        int          lda1 = (t == 0) ? 0 : Hd;
        const int*   gi   = (t == 0) ? nullptr : (target_var + (size_t)(t - 1) * Bsz);
        const float* hprev = (t == 0) ? h : (hall + (size_t)(t - 1) * Bsz * Hd);
        gemm_dual<<<gemm_grid, 256>>>(g, G4H, A1, lda1, gi, dec_Wih, Hd,
                                      hprev, dec_Whh, Hd, dec_bih, dec_bhh);
        lstm_update<<<cell_blocks, 256>>>(g, c, hall + (size_t)t * Bsz * Hd, c,
                                          nullptr, nullptr);
    }

    // 6) batched logits: (T*B, H) @ (V, H)^T + b -> d_out
    gemm_dual<<<dim3(Vb / 128, (Tln * Bsz) / 128), 256>>>(
        out, Vb, hall, Hd, nullptr, dec_outW, Hd,
        nullptr, nullptr, 0, dec_outb, nullptr);
}

// round 4
// speedup vs baseline: 2.7431x; 1.2199x over previous
#include <cuda_runtime.h>
#include <cuda_bf16.h>
#include <cstdint>

// ---------------- problem constants ----------------
#define Bsz 512
#define Wln 50
#define Tln 50
#define Hd  1024
#define Vb  1024
#define MVd 64
#define Ld  30
#define G4H 4096
#define SOS_INDEX 0
#define EOS_INDEX 1

// ---------------- scratch (device globals; no runtime alloc) ----------------
__device__ float d_g   [Bsz * G4H];
__device__ float d_h   [Bsz * Hd];
__device__ float d_c   [Bsz * Hd];
__device__ float d_mm  [Ld * Bsz];
__device__ float d_m   [Bsz];

#define ALN __align__(16)
__device__ ALN __nv_bfloat16 e_hi  [Vb * Hd],  e_lo  [Vb * Hd];
__device__ ALN __nv_bfloat16 wset_h[G4H * Hd], wset_l[G4H * Hd];
__device__ ALN __nv_bfloat16 wgen_h[G4H * Hd], wgen_l[G4H * Hd];
__device__ ALN __nv_bfloat16 wmi_h [G4H * MVd], wmi_l [G4H * MVd];
__device__ ALN __nv_bfloat16 wmh_h [G4H * Hd], wmh_l [G4H * Hd];
__device__ ALN __nv_bfloat16 wdi_h [G4H * Hd], wdi_l [G4H * Hd];
__device__ ALN __nv_bfloat16 wdh_h [G4H * Hd], wdh_l [G4H * Hd];
__device__ ALN __nv_bfloat16 wo_h  [Vb * Hd],  wo_l  [Vb * Hd];
__device__ ALN __nv_bfloat16 h_hi  [Bsz * Hd], h_lo  [Bsz * Hd];
__device__ ALN __nv_bfloat16 r_hi  [Bsz * Hd], r_lo  [Bsz * Hd];
__device__ ALN __nv_bfloat16 msg_hi[Ld * Bsz * MVd], msg_lo[Ld * Bsz * MVd];
__device__ ALN __nv_bfloat16 hall_hi[Tln * Bsz * Hd], hall_lo[Tln * Bsz * Hd];

// ---------------- ptx helpers ----------------
__device__ __forceinline__ uint32_t smem_to_u32(const void* p) {
    uint32_t a;
    asm("{ .reg .u64 t; cvta.to.shared.u64 t, %1; cvt.u32.u64 %0, t; }" : "=r"(a) : "l"(p));
    return a;
}
#define CP_ASYNC16(dst, src) \
    asm volatile("cp.async.cg.shared.global [%0], [%1], 16;" :: "r"(dst), "l"(src))
#define CP_COMMIT() asm volatile("cp.async.commit_group;" ::: "memory")
#define CP_WAIT0()  asm volatile("cp.async.wait_group 0;" ::: "memory")
#define CP_WAIT1()  asm volatile("cp.async.wait_group 1;" ::: "memory")
#define LDSM4(r, a) \
    asm volatile("ldmatrix.sync.aligned.m8n8.x4.shared.b16 {%0,%1,%2,%3}, [%4];" \
        : "=r"((r)[0]), "=r"((r)[1]), "=r"((r)[2]), "=r"((r)[3]) : "r"(a))
#define SWZ(x) ((x) ^ (((x) >> 3) & 0x70))

__device__ __forceinline__ void mma16816(float* c, const uint32_t* a, const uint32_t* b)
{
    asm volatile(
        "mma.sync.aligned.m16n8k16.row.col.f32.bf16.bf16.f32 "
        "{%0,%1,%2,%3}, {%4,%5,%6,%7}, {%8,%9}, {%0,%1,%2,%3};\n"
        : "+f"(c[0]), "+f"(c[1]), "+f"(c[2]), "+f"(c[3])
        : "r"(a[0]), "r"(a[1]), "r"(a[2]), "r"(a[3]), "r"(b[0]), "r"(b[1]));
}

// ---------------- smem layout for gemm_tc ----------------
#define SM_IDX    0          // 128 ints (gather indices)
#define SM_TILES  1024
#define TILE_B    16384      // one plane: 128 rows x 128B (64 bf16)
#define STAGE_B   (4 * TILE_B)   // Ahi, Alo, Whi, Wlo
#define SMEM_TOTAL (SM_TILES + 2 * STAGE_B)

// ---------------- bf16x3 HMMA GEMM (planar pre-split operands) --------------
// C[M,N] = A1@W1^T + A2@W2^T + b1 + b2. A row-major (M,K*), W row-major (N,K*).
// K1, K2 multiples of 64. A1 supports gather (gidx) and broadcast (lda1 = 0).
__global__ void __launch_bounds__(256, 1)
gemm_tc(float* __restrict__ C, int N,
        const __nv_bfloat16* ah1, const __nv_bfloat16* al1, int lda1,
        const int* __restrict__ gidx,
        const __nv_bfloat16* wh1, const __nv_bfloat16* wl1, int K1,
        const __nv_bfloat16* ah2, const __nv_bfloat16* al2,
        const __nv_bfloat16* wh2, const __nv_bfloat16* wl2, int K2,
        const float* __restrict__ b1, const float* __restrict__ b2)
{
    extern __shared__ char smem[];
    const uint32_t sb = smem_to_u32(smem);
    const int bm = blockIdx.y * 128, bn = blockIdx.x * 128;
    const int tid = threadIdx.x, wid = tid >> 5, lane = tid & 31;
    const int wm = (wid >> 2) * 64;          // warp tile 64 x 32
    const int wn = (wid & 3) * 32;
    int* sidx = (int*)(smem + SM_IDX);

    if (gidx && tid < 128) sidx[tid] = gidx[bm + tid];
    if (gidx) __syncthreads();

    const int nb = (K1 + K2) >> 6;
    const int use_g = (gidx != nullptr);

    // ---- stage loader: 16 cp.async of 16B per thread ----
    auto load_stage = [&](int kb, int buf) {
        const uint32_t stage = sb + SM_TILES + buf * STAGE_B;
        #pragma unroll
        for (int j = 0; j < 4; j++) {
            int q = tid * 4 + j;                 // 0..1023
            int row = q >> 3, ch = q & 7;        // 128 rows x 8 chunks(16B)
            int kg = kb * 64 + ch * 8;
            uint32_t so = SWZ((uint32_t)(row * 128 + ch * 16));
            const __nv_bfloat16 *pah, *pal, *pwh, *pwl;
            if (kg < K1) {
                size_t ar = use_g ? (size_t)sidx[row] * lda1 : (size_t)(bm + row) * lda1;
                pah = ah1 + ar + kg;  pal = al1 + ar + kg;
                size_t wr = (size_t)(bn + row) * K1 + kg;
                pwh = wh1 + wr;       pwl = wl1 + wr;
            } else {
                int k2 = kg - K1;
                size_t ar = (size_t)(bm + row) * K2 + k2;
                pah = ah2 + ar;       pal = al2 + ar;
                size_t wr = (size_t)(bn + row) * K2 + k2;
                pwh = wh2 + wr;       pwl = wl2 + wr;
            }
            CP_ASYNC16(stage + 0 * TILE_B + so, pah);
            CP_ASYNC16(stage + 1 * TILE_B + so, pal);
            CP_ASYNC16(stage + 2 * TILE_B + so, pwh);
            CP_ASYNC16(stage + 3 * TILE_B + so, pwl);
        }
        CP_COMMIT();
    };

    float acc[4][4][4];
    #pragma unroll
    for (int mt = 0; mt < 4; mt++)
        #pragma unroll
        for (int nt = 0; nt < 4; nt++)
            #pragma unroll
            for (int i = 0; i < 4; i++) acc[mt][nt][i] = 0.f;

    load_stage(0, 0);
    if (nb > 1) load_stage(1, 1);

    for (int kb = 0; kb < nb; kb++) {
        if (kb + 1 < nb) { CP_WAIT1(); } else { CP_WAIT0(); }
        __syncthreads();
        const uint32_t stage = sb + SM_TILES + (kb & 1) * STAGE_B;

        #pragma unroll
        for (int ks = 0; ks < 4; ks++) {
            uint32_t ah[4][4], al[4][4], bh[4][2], bl[4][2];
            // A fragments
            {
                const int arow = wm + (lane & 15);
                const int acol = ks * 32 + ((lane >> 4) << 4);
                #pragma unroll
                for (int mt = 0; mt < 4; mt++) {
                    uint32_t byte = (uint32_t)((arow + mt * 16) * 128 + acol);
                    uint32_t off = SWZ(byte);
                    LDSM4(ah[mt], stage + 0 * TILE_B + off);
                    LDSM4(al[mt], stage + 1 * TILE_B + off);
                }
            }
            // B fragments
            {
                const int brow = wn + (lane & 7) + ((lane >> 4) << 3);
                const int bcol = ks * 32 + (((lane >> 3) & 1) << 4);
                #pragma unroll
                for (int p2 = 0; p2 < 2; p2++) {
                    uint32_t byte = (uint32_t)((brow + p2 * 16) * 128 + bcol);
                    uint32_t off = SWZ(byte);
                    uint32_t r[4];
                    LDSM4(r, stage + 2 * TILE_B + off);
                    bh[p2 * 2][0] = r[0]; bh[p2 * 2][1] = r[1];
                    bh[p2 * 2 + 1][0] = r[2]; bh[p2 * 2 + 1][1] = r[3];
                    LDSM4(r, stage + 3 * TILE_B + off);
                    bl[p2 * 2][0] = r[0]; bl[p2 * 2][1] = r[1];
                    bl[p2 * 2 + 1][0] = r[2]; bl[p2 * 2 + 1][1] = r[3];
                }
            }
            #pragma unroll
            for (int mt = 0; mt < 4; mt++)
                #pragma unroll
                for (int nt = 0; nt < 4; nt++) {
                    mma16816(acc[mt][nt], ah[mt], bh[nt]);
                    mma16816(acc[mt][nt], ah[mt], bl[nt]);
                    mma16816(acc[mt][nt], al[mt], bh[nt]);
                }
        }
        __syncthreads();
        if (kb + 2 < nb) load_stage(kb + 2, kb & 1);
    }

    // ---- epilogue with biases ----
    #pragma unroll
    for (int nt = 0; nt < 4; nt++) {
        const int n0 = bn + wn + nt * 8 + 2 * (lane & 3);
        float bias0 = 0.f, bias1 = 0.f;
        if (b1) { bias0 += b1[n0]; bias1 += b1[n0 + 1]; }
        if (b2) { bias0 += b2[n0]; bias1 += b2[n0 + 1]; }
        #pragma unroll
        for (int mt = 0; mt < 4; mt++) {
            const int m0 = bm + wm + mt * 16 + (lane >> 2);
            float2 v0 = make_float2(acc[mt][nt][0] + bias0, acc[mt][nt][1] + bias1);
            float2 v1 = make_float2(acc[mt][nt][2] + bias0, acc[mt][nt][3] + bias1);
            *(float2*)&C[(size_t)m0 * N + n0] = v0;
            *(float2*)&C[(size_t)(m0 + 8) * N + n0] = v1;
        }
    }
}

// ---------------- fp32 -> bf16 hi/lo split ----------------
__global__ void conv_split(const float* __restrict__ s, __nv_bfloat16* __restrict__ hi,
                           __nv_bfloat16* __restrict__ lo, int n)
{
    int i = blockIdx.x * blockDim.x + threadIdx.x;
    if (i >= n) return;
    float x = s[i];
    __nv_bfloat16 h = __float2bfloat16(x);
    hi[i] = h;
    lo[i] = __float2bfloat16(x - __bfloat162float(h));
}

__global__ void zero_bf16(__nv_bfloat16* p, int n)
{
    int i = blockIdx.x * blockDim.x + threadIdx.x;
    if (i < n) p[i] = __float2bfloat16(0.f);
}
__global__ void fill_val(float* p, float v, int n)
{
    int i = blockIdx.x * blockDim.x + threadIdx.x;
    if (i < n) p[i] = v;
}

// ---------------- LSTM elementwise update ----------------
__global__ void lstm_update(const float* __restrict__ g, const float* c_in,
                            float* __restrict__ h_f32,
                            __nv_bfloat16* __restrict__ hh, __nv_bfloat16* __restrict__ hl,
                            float* c_out, const float* __restrict__ mask,
                            const float* h_old)
{
    int idx = blockIdx.x * blockDim.x + threadIdx.x;
    if (idx >= Bsz * Hd) return;
    int b = idx >> 10, hhx = idx & 1023;
    const float* gb = g + ((size_t)b << 12);
    float gi = gb[hhx], gf = gb[1024 + hhx], gc = gb[2048 + hhx], go = gb[3072 + hhx];
    float cold = c_in ? c_in[idx] : 0.f;
    float si = 1.f / (1.f + expf(-gi));
    float sf = 1.f / (1.f + expf(-gf));
    float so = 1.f / (1.f + expf(-go));
    float cn = sf * cold + si * tanhf(gc);
    float hn = so * tanhf(cn);
    if (mask) {
        float mt = mask[b];
        hn = mt * hn + (1.f - mt) * h_old[idx];
        cn = mt * cn + (1.f - mt) * cold;
    }
    h_f32[idx] = hn;
    c_out[idx] = cn;
    __nv_bfloat16 hb = __float2bfloat16(hn);
    hh[idx] = hb;
    hl[idx] = __float2bfloat16(hn - __bfloat162float(hb));
}

// ---------------- attention + pooled representation -------------------------
__global__ void attn_r(const int* __restrict__ inp, const float* __restrict__ mask,
                       const float* __restrict__ emb, const float* __restrict__ attn_w,
                       const float* __restrict__ attn_b,
                       __nv_bfloat16* __restrict__ rh, __nv_bfloat16* __restrict__ rl)
{
    const int b = blockIdx.x;
    const int tid = threadIdx.x;
    const int lane = tid & 31, wrp = tid >> 5;
    __shared__ float aw[Wln];
    __shared__ int   idxs[Wln];
    if (tid < Wln) idxs[tid] = inp[b * Wln + tid];
    __syncthreads();
    const float* w2 = attn_w + Hd;
    for (int wi = wrp; wi < Wln; wi += 8) {
        const float* e = emb + (size_t)idxs[wi] * Hd;
        float acc = 0.f;
        for (int k = lane; k < Hd; k += 32) acc += e[k] * w2[k];
        #pragma unroll
        for (int o = 16; o; o >>= 1) acc += __shfl_xor_sync(0xffffffffu, acc, o);
        if (lane == 0) {
            float a = 1.f / (1.f + expf(-(acc + attn_b[0])));
            aw[wi] = a * mask[wi * Bsz + b];
        }
    }
    __syncthreads();
    for (int hh = tid; hh < Hd; hh += 256) {
        float acc = 0.f;
        #pragma unroll 5
        for (int wi = 0; wi < Wln; wi++)
            acc += aw[wi] * emb[(size_t)idxs[wi] * Hd + hh];
        __nv_bfloat16 hb = __float2bfloat16(acc);
        rh[b * Hd + hh] = hb;
        rl[b * Hd + hh] = __float2bfloat16(acc - __bfloat162float(hb));
    }
}

// ---------------- gen output head: GEMV + softmax + eos mask ----------------
__global__ void gen_out(const float* __restrict__ h, const float* __restrict__ outW,
                        const float* __restrict__ outb,
                        __nv_bfloat16* __restrict__ mh, __nv_bfloat16* __restrict__ ml,
                        float* __restrict__ msgmask, float* __restrict__ m_state, int l)
{
    const int b = blockIdx.x;
    const int j = threadIdx.x;                  // 64 threads
    __shared__ float4 hs4[Hd / 4];
    __shared__ float  red[2];
    const float4* hrow = (const float4*)(h + (size_t)b * Hd);
    for (int k = j; k < Hd / 4; k += 64) hs4[k] = hrow[k];
    __syncthreads();

    float acc = outb[j];
    const float4* w4 = (const float4*)(outW + (size_t)j * Hd);
    #pragma unroll 4
    for (int k = 0; k < Hd / 4; k++) {
        float4 wv = w4[k];
        float4 hv = hs4[k];
        acc += wv.x * hv.x + wv.y * hv.y + wv.z * hv.z + wv.w * hv.w;
    }
    float vmax = acc;
    #pragma unroll
    for (int o = 16; o; o >>= 1) vmax = fmaxf(vmax, __shfl_xor_sync(0xffffffffu, vmax, o));
    if ((j & 31) == 0) red[j >> 5] = vmax;
    __syncthreads();
    vmax = fmaxf(red[0], red[1]);
    float e = expf(acc - vmax);
    float s = e;
    #pragma unroll
    for (int o = 16; o; o >>= 1) s += __shfl_xor_sync(0xffffffffu, s, o);
    __syncthreads();
    if ((j & 31) == 0) red[j >> 5] = s;
    __syncthreads();
    s = red[0] + red[1];
    float p = e / s;
    size_t oi = (size_t)l * Bsz * MVd + b * MVd + j;
    __nv_bfloat16 pb = __float2bfloat16(p);
    mh[oi] = pb;
    ml[oi] = __float2bfloat16(p - __bfloat162float(pb));
    if (j == EOS_INDEX) {
        float mo = m_state[b];
        msgmask[l * Bsz + b] = mo;
        m_state[b] = mo * (1.f - p);
    }
}

// ---------------- host orchestration ----------------
static inline void conv(const float* src, __nv_bfloat16* hi, __nv_bfloat16* lo, int n)
{
    conv_split<<<(n + 255) / 256, 256>>>(src, hi, lo, n);
}

extern "C" void kernel_launch(void* const* d_in, const int* in_sizes, int n_in,
                              void* d_out, int out_size)
{
    const int s = (in_sizes[3] == 1) ? 1 : 0;

    const int*   input_var  = (const int*)  d_in[0];
    const float* input_mask = (const float*)d_in[1];
    const int*   target_var = (const int*)  d_in[2];
    const float* embedding  = (const float*)d_in[3 + s];
    const float* attn_w     = (const float*)d_in[4 + s];
    const float* attn_b     = (const float*)d_in[5 + s];
    const float* set_Wih    = (const float*)d_in[6 + s];
    const float* set_bih    = (const float*)d_in[8 + s];
    const float* set_bhh    = (const float*)d_in[9 + s];
    const float* gen_Whh    = (const float*)d_in[14 + s];
    const float* gen_bih    = (const float*)d_in[15 + s];
    const float* gen_bhh    = (const float*)d_in[16 + s];
    const float* gen_outW   = (const float*)d_in[17 + s];
    const float* gen_outb   = (const float*)d_in[18 + s];
    const float* menc_Wih   = (const float*)d_in[19 + s];
    const float* menc_Whh   = (const float*)d_in[20 + s];
    const float* menc_bih   = (const float*)d_in[21 + s];
    const float* menc_bhh   = (const float*)d_in[22 + s];
    const float* dec_Wih    = (const float*)d_in[25 + s];
    const float* dec_Whh    = (const float*)d_in[26 + s];
    const float* dec_bih    = (const float*)d_in[27 + s];
    const float* dec_bhh    = (const float*)d_in[28 + s];
    const float* dec_outW   = (const float*)d_in[29 + s];
    const float* dec_outb   = (const float*)d_in[30 + s];
    float* out = (float*)d_out;

    float *g, *h, *c, *mm, *m;
    cudaGetSymbolAddress((void**)&g,  d_g);
    cudaGetSymbolAddress((void**)&h,  d_h);
    cudaGetSymbolAddress((void**)&c,  d_c);
    cudaGetSymbolAddress((void**)&mm, d_mm);
    cudaGetSymbolAddress((void**)&m,  d_m);
    __nv_bfloat16 *ehi, *elo, *wsh, *wsl, *wgh, *wgl, *wmih, *wmil, *wmhh, *wmhl;
    __nv_bfloat16 *wdih, *wdil, *wdhh, *wdhl, *woh, *wol, *hh, *hl, *rh, *rl;
    __nv_bfloat16 *msh, *msl, *hah, *hal;
    cudaGetSymbolAddress((void**)&ehi, e_hi);    cudaGetSymbolAddress((void**)&elo, e_lo);
    cudaGetSymbolAddress((void**)&wsh, wset_h);  cudaGetSymbolAddress((void**)&wsl, wset_l);
    cudaGetSymbolAddress((void**)&wgh, wgen_h);  cudaGetSymbolAddress((void**)&wgl, wgen_l);
    cudaGetSymbolAddress((void**)&wmih, wmi_h);  cudaGetSymbolAddress((void**)&wmil, wmi_l);
    cudaGetSymbolAddress((void**)&wmhh, wmh_h);  cudaGetSymbolAddress((void**)&wmhl, wmh_l);
    cudaGetSymbolAddress((void**)&wdih, wdi_h);  cudaGetSymbolAddress((void**)&wdil, wdi_l);
    cudaGetSymbolAddress((void**)&wdhh, wdh_h);  cudaGetSymbolAddress((void**)&wdhl, wdh_l);
    cudaGetSymbolAddress((void**)&woh, wo_h);    cudaGetSymbolAddress((void**)&wol, wo_l);
    cudaGetSymbolAddress((void**)&hh,  h_hi);    cudaGetSymbolAddress((void**)&hl,  h_lo);
    cudaGetSymbolAddress((void**)&rh,  r_hi);    cudaGetSymbolAddress((void**)&rl,  r_lo);
    cudaGetSymbolAddress((void**)&msh, msg_hi);  cudaGetSymbolAddress((void**)&msl, msg_lo);
    cudaGetSymbolAddress((void**)&hah, hall_hi); cudaGetSymbolAddress((void**)&hal, hall_lo);

    cudaFuncSetAttribute(gemm_tc, cudaFuncAttributeMaxDynamicSharedMemorySize, SMEM_TOTAL);

    const dim3 rg(G4H / 128, Bsz / 128);         // recurrent GEMM grid (32,4)
    const int  cb = (Bsz * Hd) / 256;

    // 0) operand conversion (hi/lo split, once per launch)
    conv(embedding, ehi, elo, Vb * Hd);
    conv(set_Wih,  wsh,  wsl,  G4H * Hd);
    conv(gen_Whh,  wgh,  wgl,  G4H * Hd);
    conv(menc_Wih, wmih, wmil, G4H * MVd);
    conv(menc_Whh, wmhh, wmhl, G4H * Hd);
    conv(dec_Wih,  wdih, wdil, G4H * Hd);
    conv(dec_Whh,  wdhh, wdhl, G4H * Hd);
    conv(dec_outW, woh,  wol,  Vb * Hd);

    // 1) attention + pooled r (hi/lo)
    attn_r<<<Bsz, 256>>>(input_var, input_mask, embedding, attn_w, attn_b, rh, rl);

    // 2) set encoder cell (h0 = c0 = 0)
    gemm_tc<<<rg, 256, SMEM_TOTAL>>>(g, G4H, rh, rl, Hd, nullptr, wsh, wsl, Hd,
                                     nullptr, nullptr, nullptr, nullptr, 0,
                                     set_bih, set_bhh);
    lstm_update<<<cb, 256>>>(g, nullptr, h, hh, hl, c, nullptr, nullptr);

    // 3) gen loop (x == 0 -> only h@Whh + biases)
    fill_val<<<2, 256>>>(m, 1.f, Bsz);
    for (int l = 0; l < Ld; l++) {
        gemm_tc<<<rg, 256, SMEM_TOTAL>>>(g, G4H, nullptr, nullptr, 0, nullptr,
                                         nullptr, nullptr, 0,
                                         hh, hl, wgh, wgl, Hd, gen_bih, gen_bhh);
        lstm_update<<<cb, 256>>>(g, c, h, hh, hl, c, nullptr, nullptr);
        gen_out<<<Bsz, 64>>>(h, gen_outW, gen_outb, msh, msl, mm, m, l);
    }

    // 4) message encoder loop (h0 = c0 = 0)
    fill_val<<<cb, 256>>>(h, 0.f, Bsz * Hd);
    fill_val<<<cb, 256>>>(c, 0.f, Bsz * Hd);
    zero_bf16<<<cb, 256>>>(hh, Bsz * Hd);
    zero_bf16<<<cb, 256>>>(hl, Bsz * Hd);
    for (int l = 0; l < Ld; l++) {
        gemm_tc<<<rg, 256, SMEM_TOTAL>>>(g, G4H,
                                         msh + (size_t)l * Bsz * MVd,
                                         msl + (size_t)l * Bsz * MVd, MVd, nullptr,
                                         wmih, wmil, MVd,
                                         hh, hl, wmhh, wmhl, Hd, menc_bih, menc_bhh);
        lstm_update<<<cb, 256>>>(g, c, h, hh, hl, c, mm + l * Bsz, h);
    }

    // 5) decoder loop: fused [x;h] GEMM, embedding gather, h -> hall hi/lo ring
    for (int t = 0; t < Tln; t++) {
        const __nv_bfloat16* A1h = ehi + (size_t)SOS_INDEX * Hd;
        const __nv_bfloat16* A1l = elo + (size_t)SOS_INDEX * Hd;
        int        lda1 = (t == 0) ? 0 : Hd;
        const int* gi   = (t == 0) ? nullptr : (target_var + (size_t)(t - 1) * Bsz);
        const __nv_bfloat16* A2h = (t == 0) ? hh : (hah + (size_t)(t - 1) * Bsz * Hd);
        const __nv_bfloat16* A2l = (t == 0) ? hl : (hal + (size_t)(t - 1) * Bsz * Hd);
        gemm_tc<<<rg, 256, SMEM_TOTAL>>>(g, G4H, (t == 0) ? A1h : ehi,
                                         (t == 0) ? A1l : elo, lda1, gi,
                                         wdih, wdil, Hd,
                                         A2h, A2l, wdhh, wdhl, Hd, dec_bih, dec_bhh);
        lstm_update<<<cb, 256>>>(g, c, h,
                                 hah + (size_t)t * Bsz * Hd, hal + (size_t)t * Bsz * Hd,
                                 c, nullptr, nullptr);
    }

    // 6) batched logits: (T*B, H) @ (V, H)^T + b -> d_out
    gemm_tc<<<dim3(Vb / 128, (Tln * Bsz) / 128), 256, SMEM_TOTAL>>>(
        out, Vb, nullptr, nullptr, 0, nullptr, nullptr, nullptr, 0,
        hah, hal, woh, wol, Hd, dec_outb, nullptr);
}